// round 14
// baseline (speedup 1.0000x reference)
#include <cuda_runtime.h>
#include <cuda_fp16.h>
#include <cstdint>

#define NN 8192
#define FIN 512
#define FOUT 256
#define CTA_M 64
#define JHALF (NN / 2)
#define CH2 64
#define NCH2 (JHALF / CH2)      // 64 chunks per half
#define BSTRIDE 40              // k_xw smem stride (halves)
#define ASTRIDE 72              // k_attn A-tile stride (halves), conflict-free
#define TILE_HALVES 8192        // one 32-j tile: 256 rows * 32 halves
#define TILE_BYTES 16384
#define CHUNK_BYTES 32768       // two tiles per chunk
#define ABUF_BYTES (CTA_M * ASTRIDE * 2)

// ---------------- scratch (device globals; no allocation allowed) -----------
// hT16: block-tiled + pre-swizzled: tile t = j/32, row c, j' = j%32.
// byte addr = t*16384 + c*64 + (((j'>>3) ^ ((c>>1)&3))<<4) + (j'&7)*2
__device__ __half  g_hT16[(size_t)FOUT * NN];
__device__ __half  g_W16T[(size_t)FOUT * FIN];  // [n][k], k contiguous, fp16
__device__ float   g_wl[FIN], g_wr[FIN];
__device__ float4  g_EFG[NN];                   // per-j: (E, F, G, 0)
__device__ float2  g_RT [NN];                   // per-i: (R=e^{-0.8f}, T=-f)
__device__ float   g_S[2][(size_t)NN * FOUT];   // partial numerators per j-half
__device__ float   g_Z[2][NN];                  // partial row sums per j-half

// ---------------- helpers ----------------------------------------------------
static __device__ __forceinline__ uint32_t smem_u32(const void* p) {
    uint32_t a;
    asm("{ .reg .u64 t; cvta.to.shared.u64 t, %1; cvt.u32.u64 %0, t; }" : "=r"(a) : "l"(p));
    return a;
}
static __device__ __forceinline__ void cp16(uint32_t dst, const void* src) {
    asm volatile("cp.async.ca.shared.global [%0], [%1], 16;" :: "r"(dst), "l"(src));
}
static __device__ __forceinline__ void cp_commit() {
    asm volatile("cp.async.commit_group;");
}
static __device__ __forceinline__ void cp_wait_all() {
    asm volatile("cp.async.wait_group 0;");
}
static __device__ __forceinline__ void ldsm4(uint32_t* r, uint32_t addr) {
    asm volatile("ldmatrix.sync.aligned.m8n8.x4.shared.b16 {%0,%1,%2,%3}, [%4];"
                 : "=r"(r[0]), "=r"(r[1]), "=r"(r[2]), "=r"(r[3]) : "r"(addr));
}
static __device__ __forceinline__ void mma16816(float* d, const uint32_t* a,
                                                uint32_t b0, uint32_t b1) {
    asm volatile(
        "mma.sync.aligned.m16n8k16.row.col.f32.f16.f16.f32 "
        "{%0,%1,%2,%3}, {%4,%5,%6,%7}, {%8,%9}, {%0,%1,%2,%3};"
        : "+f"(d[0]), "+f"(d[1]), "+f"(d[2]), "+f"(d[3])
        : "r"(a[0]), "r"(a[1]), "r"(a[2]), "r"(a[3]), "r"(b0), "r"(b1));
}

#define MBAR_INIT(addr, cnt) \
    asm volatile("mbarrier.init.shared.b64 [%0], %1;" :: "r"(addr), "r"(cnt) : "memory")
#define MBAR_EXPECT_TX(addr, tx) \
    asm volatile("mbarrier.arrive.expect_tx.shared.b64 _, [%0], %1;" :: "r"(addr), "r"(tx) : "memory")
#define CP_BULK(dst, src, bytes, mbar) \
    asm volatile("cp.async.bulk.shared::cta.global.mbarrier::complete_tx::bytes " \
                 "[%0], [%1], %2, [%3];" \
                 :: "r"(dst), "l"(src), "r"(bytes), "r"(mbar) : "memory")
#define MBAR_WAIT(addr, par) do {                                              \
    uint32_t _m = (addr), _p = (par), _d;                                      \
    asm volatile("{\n\t.reg .pred p;\n\t"                                      \
        "mbarrier.try_wait.parity.acquire.cta.shared::cta.b64 p, [%1], %2;\n\t"\
        "selp.b32 %0, 1, 0, p;\n\t}"                                           \
        : "=r"(_d) : "r"(_m), "r"(_p) : "memory");                             \
    if (!_d) {                                                                 \
        asm volatile("{\n\t.reg .pred P1;\n\t"                                 \
            "WL_%=:\n\t"                                                       \
            "mbarrier.try_wait.parity.acquire.cta.shared::cta.b64 P1, [%0], %1, 0x989680;\n\t" \
            "@P1 bra.uni WD_%=;\n\t"                                           \
            "bra.uni WL_%=;\n\t"                                               \
            "WD_%=:\n\t}" :: "r"(_m), "r"(_p) : "memory");                     \
    }                                                                          \
} while (0)

// ---------------------------------------------------------------------------
// Prep A: W -> fp16 transposed [n][k]
// ---------------------------------------------------------------------------
__global__ void __launch_bounds__(256) k_prep_w(const float* __restrict__ W) {
    const int tid = threadIdx.x;
#pragma unroll
    for (int r = 0; r < 8; r++) {
        const int k = blockIdx.x * 8 + r;
        g_W16T[(size_t)tid * FIN + k] = __float2half_rn(W[(size_t)k * FOUT + tid]);
    }
}

// ---------------------------------------------------------------------------
// Prep B: wl = W @ a[0:256], wr = W @ a[256:512]  (exact fp32)
// ---------------------------------------------------------------------------
__global__ void __launch_bounds__(256) k_wvec(const float* __restrict__ W,
                                              const float* __restrict__ a) {
    const int wid  = threadIdx.x >> 5;
    const int lane = threadIdx.x & 31;
    const int k    = blockIdx.x * 8 + wid;
    float l = 0.f, r = 0.f;
#pragma unroll
    for (int q = 0; q < 8; q++) {
        const int c = q * 32 + lane;
        const float wv = W[(size_t)k * FOUT + c];
        l += wv * a[c];
        r += wv * a[FOUT + c];
    }
#pragma unroll
    for (int off = 16; off; off >>= 1) {
        l += __shfl_down_sync(0xffffffffu, l, off);
        r += __shfl_down_sync(0xffffffffu, r, off);
    }
    if (lane == 0) { g_wl[k] = l; g_wr[k] = r; }
}

// ---------------------------------------------------------------------------
// Scores directly from x (fp32 exact)
// ---------------------------------------------------------------------------
__global__ void __launch_bounds__(256) k_scores(const float* __restrict__ x) {
    const int wid  = threadIdx.x >> 5;
    const int lane = threadIdx.x & 31;
    const int i    = blockIdx.x * 8 + wid;

    float f = 0.f, g = 0.f;
#pragma unroll
    for (int q = 0; q < 4; q++) {
        const int k = q * 128 + lane * 4;
        float4 xv = *reinterpret_cast<const float4*>(&x[(size_t)i * FIN + k]);
        float4 lv = *reinterpret_cast<const float4*>(&g_wl[k]);
        float4 rv = *reinterpret_cast<const float4*>(&g_wr[k]);
        f += xv.x * lv.x + xv.y * lv.y + xv.z * lv.z + xv.w * lv.w;
        g += xv.x * rv.x + xv.y * rv.y + xv.z * rv.z + xv.w * rv.w;
    }
#pragma unroll
    for (int off = 16; off; off >>= 1) {
        f += __shfl_down_sync(0xffffffffu, f, off);
        g += __shfl_down_sync(0xffffffffu, g, off);
    }
    if (lane == 0) {
        g_EFG[i] = make_float4(expf(g), expf(0.2f * g), g, 0.f);
        g_RT[i]  = make_float2(expf(-0.8f * f), -f);
    }
}

// ---------------------------------------------------------------------------
// h = x @ W via fp16 mma; epilogue writes block-tiled PRE-SWIZZLED g_hT16.
// (unchanged from Round 10)
// ---------------------------------------------------------------------------
#define XA_OFF 0
#define XB_OFF 10240
#define XD_OFF 10240
#define XW_SMEM 51200

__global__ void __launch_bounds__(256) k_xw_f16(const float* __restrict__ x) {
    extern __shared__ char smem[];
    const int tid  = threadIdx.x;
    const int lane = tid & 31;
    const int wid  = tid >> 5;
    const int wm   = wid >> 2;
    const int wn   = wid & 3;
    const int i0   = blockIdx.x * CTA_M;

    const int xr = tid >> 2;
    const int xk = (tid & 3) * 8;

    float acc[2][8][4];
#pragma unroll
    for (int mt = 0; mt < 2; mt++)
#pragma unroll
        for (int nt = 0; nt < 8; nt++)
#pragma unroll
            for (int q = 0; q < 4; q++) acc[mt][nt][q] = 0.f;

    const uint32_t sb = smem_u32(smem);
    const uint32_t aBase = sb + XA_OFF + ((wm * 32 + (lane & 15)) * BSTRIDE + (lane >> 4) * 8) * 2;
    const uint32_t bBase = sb + XB_OFF + ((wn * 64 + (lane & 15)) * BSTRIDE + (lane >> 4) * 8) * 2;

    float4 xa = *reinterpret_cast<const float4*>(&x[(size_t)(i0 + xr) * FIN + xk]);
    float4 xb = *reinterpret_cast<const float4*>(&x[(size_t)(i0 + xr) * FIN + xk + 4]);
    {
        uint32_t bdst = sb + XB_OFF + tid * (BSTRIDE * 2);
        const __half* bsrc = g_W16T + (size_t)tid * FIN;
#pragma unroll
        for (int q = 0; q < 4; q++) cp16(bdst + 16 * q, bsrc + 8 * q);
        cp_commit();
    }

    for (int c = 0; c < FIN / 32; c++) {
        const int cur = c & 1;
        cp_wait_all();
        __syncthreads();

        {
            __half2 hx[4];
            hx[0] = __floats2half2_rn(xa.x, xa.y);
            hx[1] = __floats2half2_rn(xa.z, xa.w);
            hx[2] = __floats2half2_rn(xb.x, xb.y);
            hx[3] = __floats2half2_rn(xb.z, xb.w);
            *reinterpret_cast<uint4*>(smem + XA_OFF + (cur * CTA_M * BSTRIDE + xr * BSTRIDE + xk) * 2) =
                *reinterpret_cast<uint4*>(hx);
        }
        if (c + 1 < FIN / 32) {
            const int k0 = (c + 1) * 32;
            xa = *reinterpret_cast<const float4*>(&x[(size_t)(i0 + xr) * FIN + k0 + xk]);
            xb = *reinterpret_cast<const float4*>(&x[(size_t)(i0 + xr) * FIN + k0 + xk + 4]);
            uint32_t bdst = sb + XB_OFF + ((cur ^ 1) * FOUT * BSTRIDE + tid * BSTRIDE) * 2;
            const __half* bsrc = g_W16T + (size_t)tid * FIN + k0;
#pragma unroll
            for (int q = 0; q < 4; q++) cp16(bdst + 16 * q, bsrc + 8 * q);
        }
        cp_commit();
        __syncthreads();

        const uint32_t aOff = cur * (uint32_t)(CTA_M * BSTRIDE * 2);
        const uint32_t bOff = cur * (uint32_t)(FOUT * BSTRIDE * 2);
#pragma unroll
        for (int ks = 0; ks < 2; ks++) {
            const uint32_t kOff = ks * 32;
            uint32_t af[2][4];
            ldsm4(af[0], aBase + aOff + kOff);
            ldsm4(af[1], aBase + aOff + kOff + 16 * BSTRIDE * 2);
            uint32_t bf[4][4];
#pragma unroll
            for (int np = 0; np < 4; np++)
                ldsm4(bf[np], bBase + bOff + kOff + np * 16 * BSTRIDE * 2);
#pragma unroll
            for (int np = 0; np < 4; np++) {
#pragma unroll
                for (int mt = 0; mt < 2; mt++) {
                    mma16816(acc[mt][2 * np],     af[mt], bf[np][0], bf[np][2]);
                    mma16816(acc[mt][2 * np + 1], af[mt], bf[np][1], bf[np][3]);
                }
            }
        }
        __syncthreads();
    }

    // ---- epilogue: smem transpose -> block-tiled pre-swizzled gmem ----
    __half* Dp = reinterpret_cast<__half*>(smem + XD_OFF);   // [64][264]
#pragma unroll
    for (int mt = 0; mt < 2; mt++) {
        const int rca = wm * 32 + mt * 16 + (lane >> 2);
        const int c0  = wn * 64 + 2 * (lane & 3);
#pragma unroll
        for (int nt = 0; nt < 8; nt++) {
            const int cc = c0 + nt * 8;
            *reinterpret_cast<__half2*>(&Dp[rca * 264 + cc]) =
                __floats2half2_rn(acc[mt][nt][0], acc[mt][nt][1]);
            *reinterpret_cast<__half2*>(&Dp[(rca + 8) * 264 + cc]) =
                __floats2half2_rn(acc[mt][nt][2], acc[mt][nt][3]);
        }
    }
    __syncthreads();

    const int ib0 = blockIdx.x * 2;
    const int m   = (tid >> 1) & 3;
#pragma unroll
    for (int blk = 0; blk < 2; blk++) {
        __half* dst = g_hT16 + (size_t)(ib0 + blk) * TILE_HALVES + tid * 32;
#pragma unroll
        for (int u = 0; u < 4; u++) {
            __half2 v[4];
#pragma unroll
            for (int w = 0; w < 4; w++)
                v[w] = __halves2half2(Dp[(blk * 32 + u * 8 + 2 * w) * 264 + tid],
                                      Dp[(blk * 32 + u * 8 + 2 * w + 1) * 264 + tid]);
            *reinterpret_cast<uint4*>(dst + ((u ^ m) << 3)) = *reinterpret_cast<uint4*>(v);
        }
    }
}

// ---------------------------------------------------------------------------
// Attention: fp16 mma, j-split, CH=64, overlapped single-barrier structure:
//   chunk body = issue bulk(c+1) -> mbar wait(c) -> mma(c) -> P-gen(c+1) -> bar
// ---------------------------------------------------------------------------
__global__ void __launch_bounds__(256, 2) k_attn_f16(const int* __restrict__ adj) {
    extern __shared__ __align__(128) char bsm[];             // 2 x 32 KB B chunks
    __shared__ __align__(16)  __half A_s[2][CTA_M][ASTRIDE];
    __shared__ float zs[256];
    __shared__ __align__(8) unsigned long long mbar[2];

    const int tid  = threadIdx.x;
    const int lane = tid & 31;
    const int wid  = tid >> 5;
    const int wm   = wid >> 2;
    const int wn   = wid & 3;
    const int rb   = blockIdx.x >> 1;
    const int half = blockIdx.x & 1;
    const int i0   = rb * CTA_M;
    const int jb   = half * JHALF;
    const int jblk0 = jb >> 5;

    const int pr = tid >> 2;            // P-gen row 0..63
    const int kq = (tid & 3) * 16;      // 16 j's per thread

    const float2 rt = g_RT[i0 + pr];
    const float Ri = rt.x, Ti = rt.y;
    float zacc = 0.f;

    float acc[2][8][4];
#pragma unroll
    for (int mt = 0; mt < 2; mt++)
#pragma unroll
        for (int nt = 0; nt < 8; nt++)
#pragma unroll
            for (int q = 0; q < 4; q++) acc[mt][nt][q] = 0.f;

    const uint32_t aAddrBase = smem_u32(&A_s[0][wm * 32 + (lane & 15)][(lane >> 4) * 8]);
    const uint32_t bTile0    = smem_u32(bsm);
    const uint32_t mb0       = smem_u32(&mbar[0]);

    // B ldsm addressing (swizzled tiles): row r = wn*64 + np*16 + (lane&15)
    uint32_t bRowOff[4], bM[4];
#pragma unroll
    for (int np = 0; np < 4; np++) {
        const int r = wn * 64 + np * 16 + (lane & 15);
        bRowOff[np] = (uint32_t)r * 64u;
        bM[np] = (uint32_t)((r >> 1) & 3);
    }
    const uint32_t cHi = (uint32_t)(lane >> 4);

    if (tid == 0) {
        MBAR_INIT(mb0,     1u);
        MBAR_INIT(mb0 + 8, 1u);
    }
    __syncthreads();

    // prologue: bulk B chunk 0 -> stage 0; P-gen chunk 0 into A[0] (EFG via LDG)
    if (tid == 0) {
        MBAR_EXPECT_TX(mb0, (uint32_t)CHUNK_BYTES);
        CP_BULK(bTile0, (const char*)(g_hT16 + (size_t)jblk0 * TILE_HALVES),
                (uint32_t)CHUNK_BYTES, mb0);
    }
    const int4* arow = reinterpret_cast<const int4*>(adj + (size_t)(i0 + pr) * NN + jb);
    {
        int4 a0 = arow[(kq >> 2) + 0];
        int4 a1 = arow[(kq >> 2) + 1];
        int4 a2 = arow[(kq >> 2) + 2];
        int4 a3 = arow[(kq >> 2) + 3];
        const float4* efg = g_EFG + jb;
        int avv[16] = {a0.x, a0.y, a0.z, a0.w, a1.x, a1.y, a1.z, a1.w,
                       a2.x, a2.y, a2.z, a2.w, a3.x, a3.y, a3.z, a3.w};
        __half2 hp[8];
#pragma unroll
        for (int u = 0; u < 16; u += 2) {
            float4 e0 = __ldg(&efg[kq + u]);
            float4 e1 = __ldg(&efg[kq + u + 1]);
            float p0 = (e0.z > Ti) ? e0.x : Ri * e0.y;
            float p1 = (e1.z > Ti) ? e1.x : Ri * e1.y;
            p0 = (avv[u] > 0) ? p0 : 0.f;
            p1 = (avv[u + 1] > 0) ? p1 : 0.f;
            zacc += p0 + p1;
            hp[u >> 1] = __floats2half2_rn(p0, p1);
        }
        uint4* ad = reinterpret_cast<uint4*>(&A_s[0][pr][kq]);
        ad[0] = reinterpret_cast<uint4*>(hp)[0];
        ad[1] = reinterpret_cast<uint4*>(hp)[1];
    }
    __syncthreads();   // A[0] published

    for (int c = 0; c < NCH2; c++) {
        const int cur = c & 1, nxt = cur ^ 1;

        // issue bulk for chunk c+1 into stage nxt
        if (tid == 0 && c + 1 < NCH2) {
            const uint32_t mbn = mb0 + 8u * (uint32_t)nxt;
            MBAR_EXPECT_TX(mbn, (uint32_t)CHUNK_BYTES);
            CP_BULK(bTile0 + (uint32_t)nxt * CHUNK_BYTES,
                    (const char*)(g_hT16 + (size_t)(jblk0 + (c + 1) * 2) * TILE_HALVES),
                    (uint32_t)CHUNK_BYTES, mbn);
        }
        // adj LDG for chunk c+1 issued early
        int4 a0, a1, a2, a3;
        if (c + 1 < NCH2) {
            const int ji = ((c + 1) * CH2 + kq) >> 2;
            a0 = arow[ji];
            a1 = arow[ji + 1];
            a2 = arow[ji + 2];
            a3 = arow[ji + 3];
        }

        MBAR_WAIT(mb0 + 8u * (uint32_t)cur, (c >> 1) & 1);   // chunk c's B

        // ---- mma on chunk c: 4 k-steps of 16 ----
        const uint32_t aBufBase = aAddrBase + (uint32_t)cur * ABUF_BYTES;
        const uint32_t bChunkBase = bTile0 + (uint32_t)cur * CHUNK_BYTES;
#pragma unroll
        for (int ks = 0; ks < 4; ks++) {
            const uint32_t kOff = (uint32_t)ks * 32u;
            uint32_t af[2][4];
            ldsm4(af[0], aBufBase + kOff);
            ldsm4(af[1], aBufBase + kOff + 16 * ASTRIDE * 2);
            const uint32_t bTileBase = bChunkBase + (uint32_t)(ks >> 1) * TILE_BYTES;
            const uint32_t c16 = cHi + 2u * (uint32_t)(ks & 1);
            uint32_t bf[4][4];
#pragma unroll
            for (int np = 0; np < 4; np++)
                ldsm4(bf[np], bTileBase + bRowOff[np] + (((c16 ^ bM[np])) << 4));
#pragma unroll
            for (int np = 0; np < 4; np++) {
#pragma unroll
                for (int mt = 0; mt < 2; mt++) {
                    mma16816(acc[mt][2 * np],     af[mt], bf[np][0], bf[np][2]);
                    mma16816(acc[mt][2 * np + 1], af[mt], bf[np][1], bf[np][3]);
                }
            }
        }

        // ---- P-gen chunk c+1 into A[nxt] (overlaps HMMA drain) ----
        if (c + 1 < NCH2) {
            const float4* efg = g_EFG + jb + (c + 1) * CH2;
            int avv[16] = {a0.x, a0.y, a0.z, a0.w, a1.x, a1.y, a1.z, a1.w,
                           a2.x, a2.y, a2.z, a2.w, a3.x, a3.y, a3.z, a3.w};
            __half2 hp[8];
#pragma unroll
            for (int u = 0; u < 16; u += 2) {
                float4 e0 = __ldg(&efg[kq + u]);
                float4 e1 = __ldg(&efg[kq + u + 1]);
                float p0 = (e0.z > Ti) ? e0.x : Ri * e0.y;
                float p1 = (e1.z > Ti) ? e1.x : Ri * e1.y;
                p0 = (avv[u] > 0) ? p0 : 0.f;
                p1 = (avv[u + 1] > 0) ? p1 : 0.f;
                zacc += p0 + p1;
                hp[u >> 1] = __floats2half2_rn(p0, p1);
            }
            uint4* ad = reinterpret_cast<uint4*>(&A_s[nxt][pr][kq]);
            ad[0] = reinterpret_cast<uint4*>(hp)[0];
            ad[1] = reinterpret_cast<uint4*>(hp)[1];
        }

        __syncthreads();   // publish A[nxt]; mark B[cur]/A[cur] reads done
    }

    // ---- partial row sums ----
    zs[tid] = zacc;
    __syncthreads();
    if (tid < CTA_M)
        g_Z[half][i0 + tid] = zs[4 * tid] + zs[4 * tid + 1] + zs[4 * tid + 2] + zs[4 * tid + 3];

    // ---- store unnormalized partials ----
    float* Sp = g_S[half];
#pragma unroll
    for (int mt = 0; mt < 2; mt++) {
        const int rca = wm * 32 + mt * 16 + (lane >> 2);
        float* o0 = Sp + (size_t)(i0 + rca) * FOUT;
        float* o1 = Sp + (size_t)(i0 + rca + 8) * FOUT;
#pragma unroll
        for (int nt = 0; nt < 8; nt++) {
            const int colb = wn * 64 + nt * 8 + 2 * (lane & 3);
            *reinterpret_cast<float2*>(o0 + colb) = make_float2(acc[mt][nt][0], acc[mt][nt][1]);
            *reinterpret_cast<float2*>(o1 + colb) = make_float2(acc[mt][nt][2], acc[mt][nt][3]);
        }
    }
}

// ---------------------------------------------------------------------------
// Combine halves (vectorized): out = (S0+S1) / (Z0+Z1). 4 rows / CTA, float4.
// ---------------------------------------------------------------------------
__global__ void __launch_bounds__(256) k_combine(float* __restrict__ out) {
    const int t   = threadIdx.x;
    const int i   = blockIdx.x * 4 + (t >> 6);
    const int c4  = (t & 63) * 4;
    const float inv = 1.0f / (g_Z[0][i] + g_Z[1][i]);
    const size_t idx = (size_t)i * FOUT + c4;
    float4 s0 = *reinterpret_cast<const float4*>(&g_S[0][idx]);
    float4 s1 = *reinterpret_cast<const float4*>(&g_S[1][idx]);
    *reinterpret_cast<float4*>(&out[idx]) =
        make_float4((s0.x + s1.x) * inv, (s0.y + s1.y) * inv,
                    (s0.z + s1.z) * inv, (s0.w + s1.w) * inv);
}

// ---------------------------------------------------------------------------
extern "C" void kernel_launch(void* const* d_in, const int* in_sizes, int n_in,
                              void* d_out, int out_size) {
    const float* x   = (const float*)d_in[0];
    const int*   adj = (const int*)  d_in[1];
    const float* W   = (const float*)d_in[2];
    const float* a   = (const float*)d_in[3];
    float* out = (float*)d_out;

    cudaFuncSetAttribute(k_xw_f16, cudaFuncAttributeMaxDynamicSharedMemorySize, XW_SMEM);
    cudaFuncSetAttribute(k_attn_f16, cudaFuncAttributeMaxDynamicSharedMemorySize,
                         2 * CHUNK_BYTES);

    k_prep_w<<<FIN / 8, 256>>>(W);
    k_wvec<<<FIN / 8, 256>>>(W, a);
    k_scores<<<NN / 8, 256>>>(x);
    k_xw_f16<<<NN / CTA_M, 256, XW_SMEM>>>(x);
    k_attn_f16<<<(NN / CTA_M) * 2, 256, 2 * CHUNK_BYTES>>>(adj);
    k_combine<<<NN / 4, 256>>>(out);
}

// round 15
// speedup vs baseline: 1.0442x; 1.0442x over previous
#include <cuda_runtime.h>
#include <cuda_fp16.h>
#include <cstdint>

#define NN 8192
#define FIN 512
#define FOUT 256
#define CH 32
#define CTA_M 64
#define JHALF (NN / 2)
#define NCH_H (JHALF / CH)      // 128 chunks per half
#define BSTRIDE 40              // smem stride (halves)
#define TILE_HALVES 8192        // one 32-j tile: 256 rows * 32 halves
#define TILE_BYTES 16384
#define ABUF_BYTES (CTA_M * BSTRIDE * 2)

// ---------------- scratch (device globals; no allocation allowed) -----------
// hT16: block-tiled + pre-swizzled: tile t = j/32, row c, j' = j%32.
// byte addr = t*16384 + c*64 + (((j'>>3) ^ ((c>>1)&3))<<4) + (j'&7)*2
__device__ __half  g_hT16[(size_t)FOUT * NN];
__device__ __half  g_W16T[(size_t)FOUT * FIN];  // [n][k], k contiguous, fp16
__device__ float   g_wl[FIN], g_wr[FIN];
__device__ float4  g_EFG[NN];                   // per-j: (E, F, G, 0)
__device__ float2  g_RT [NN];                   // per-i: (R=e^{-0.8f}, T=-f)
__device__ float   g_S[2][(size_t)NN * FOUT];   // partial numerators per j-half
__device__ float   g_Z[2][NN];                  // partial row sums per j-half

// ---------------- helpers ----------------------------------------------------
static __device__ __forceinline__ uint32_t smem_u32(const void* p) {
    uint32_t a;
    asm("{ .reg .u64 t; cvta.to.shared.u64 t, %1; cvt.u32.u64 %0, t; }" : "=r"(a) : "l"(p));
    return a;
}
static __device__ __forceinline__ void cp16(uint32_t dst, const void* src) {
    asm volatile("cp.async.ca.shared.global [%0], [%1], 16;" :: "r"(dst), "l"(src));
}
static __device__ __forceinline__ void cp_commit() {
    asm volatile("cp.async.commit_group;");
}
static __device__ __forceinline__ void cp_wait_all() {
    asm volatile("cp.async.wait_group 0;");
}
static __device__ __forceinline__ void ldsm4(uint32_t* r, uint32_t addr) {
    asm volatile("ldmatrix.sync.aligned.m8n8.x4.shared.b16 {%0,%1,%2,%3}, [%4];"
                 : "=r"(r[0]), "=r"(r[1]), "=r"(r[2]), "=r"(r[3]) : "r"(addr));
}
static __device__ __forceinline__ void mma16816(float* d, const uint32_t* a,
                                                uint32_t b0, uint32_t b1) {
    asm volatile(
        "mma.sync.aligned.m16n8k16.row.col.f32.f16.f16.f32 "
        "{%0,%1,%2,%3}, {%4,%5,%6,%7}, {%8,%9}, {%0,%1,%2,%3};"
        : "+f"(d[0]), "+f"(d[1]), "+f"(d[2]), "+f"(d[3])
        : "r"(a[0]), "r"(a[1]), "r"(a[2]), "r"(a[3]), "r"(b0), "r"(b1));
}

#define MBAR_INIT(addr, cnt) \
    asm volatile("mbarrier.init.shared.b64 [%0], %1;" :: "r"(addr), "r"(cnt) : "memory")
#define MBAR_EXPECT_TX(addr, tx) \
    asm volatile("mbarrier.arrive.expect_tx.shared.b64 _, [%0], %1;" :: "r"(addr), "r"(tx) : "memory")
#define CP_BULK(dst, src, bytes, mbar) \
    asm volatile("cp.async.bulk.shared::cta.global.mbarrier::complete_tx::bytes " \
                 "[%0], [%1], %2, [%3];" \
                 :: "r"(dst), "l"(src), "r"(bytes), "r"(mbar) : "memory")
#define MBAR_WAIT(addr, par) do {                                              \
    uint32_t _m = (addr), _p = (par), _d;                                      \
    asm volatile("{\n\t.reg .pred p;\n\t"                                      \
        "mbarrier.try_wait.parity.acquire.cta.shared::cta.b64 p, [%1], %2;\n\t"\
        "selp.b32 %0, 1, 0, p;\n\t}"                                           \
        : "=r"(_d) : "r"(_m), "r"(_p) : "memory");                             \
    if (!_d) {                                                                 \
        asm volatile("{\n\t.reg .pred P1;\n\t"                                 \
            "WL_%=:\n\t"                                                       \
            "mbarrier.try_wait.parity.acquire.cta.shared::cta.b64 P1, [%0], %1, 0x989680;\n\t" \
            "@P1 bra.uni WD_%=;\n\t"                                           \
            "bra.uni WL_%=;\n\t"                                               \
            "WD_%=:\n\t}" :: "r"(_m), "r"(_p) : "memory");                     \
    }                                                                          \
} while (0)

// ---------------------------------------------------------------------------
// Prep (FUSED): W -> fp16 transposed [n][k]  AND  wl/wr = W @ a halves.
// grid 64 x 256. Both parts read only W/a (independent of everything else).
// ---------------------------------------------------------------------------
__global__ void __launch_bounds__(256) k_prep(const float* __restrict__ W,
                                              const float* __restrict__ a) {
    const int tid = threadIdx.x;
    // part 1: transpose 8 k-rows into W16T[n][k]
#pragma unroll
    for (int r = 0; r < 8; r++) {
        const int k = blockIdx.x * 8 + r;
        g_W16T[(size_t)tid * FIN + k] = __float2half_rn(W[(size_t)k * FOUT + tid]);
    }
    // part 2: wl/wr for 8 k's (one per warp)
    const int wid  = tid >> 5;
    const int lane = tid & 31;
    const int k    = blockIdx.x * 8 + wid;
    float l = 0.f, r = 0.f;
#pragma unroll
    for (int q = 0; q < 8; q++) {
        const int c = q * 32 + lane;
        const float wv = W[(size_t)k * FOUT + c];
        l += wv * a[c];
        r += wv * a[FOUT + c];
    }
#pragma unroll
    for (int off = 16; off; off >>= 1) {
        l += __shfl_down_sync(0xffffffffu, l, off);
        r += __shfl_down_sync(0xffffffffu, r, off);
    }
    if (lane == 0) { g_wl[k] = l; g_wr[k] = r; }
}

// ---------------------------------------------------------------------------
// Scores directly from x (fp32 exact)
// ---------------------------------------------------------------------------
__global__ void __launch_bounds__(256) k_scores(const float* __restrict__ x) {
    const int wid  = threadIdx.x >> 5;
    const int lane = threadIdx.x & 31;
    const int i    = blockIdx.x * 8 + wid;

    float f = 0.f, g = 0.f;
#pragma unroll
    for (int q = 0; q < 4; q++) {
        const int k = q * 128 + lane * 4;
        float4 xv = *reinterpret_cast<const float4*>(&x[(size_t)i * FIN + k]);
        float4 lv = *reinterpret_cast<const float4*>(&g_wl[k]);
        float4 rv = *reinterpret_cast<const float4*>(&g_wr[k]);
        f += xv.x * lv.x + xv.y * lv.y + xv.z * lv.z + xv.w * lv.w;
        g += xv.x * rv.x + xv.y * rv.y + xv.z * rv.z + xv.w * rv.w;
    }
#pragma unroll
    for (int off = 16; off; off >>= 1) {
        f += __shfl_down_sync(0xffffffffu, f, off);
        g += __shfl_down_sync(0xffffffffu, g, off);
    }
    if (lane == 0) {
        g_EFG[i] = make_float4(expf(g), expf(0.2f * g), g, 0.f);
        g_RT[i]  = make_float2(expf(-0.8f * f), -f);
    }
}

// ---------------------------------------------------------------------------
// h = x @ W via fp16 mma; epilogue writes block-tiled PRE-SWIZZLED g_hT16.
// (unchanged from Round 10)
// ---------------------------------------------------------------------------
#define XA_OFF 0
#define XB_OFF 10240
#define XD_OFF 10240
#define XW_SMEM 51200

__global__ void __launch_bounds__(256) k_xw_f16(const float* __restrict__ x) {
    extern __shared__ char smem[];
    const int tid  = threadIdx.x;
    const int lane = tid & 31;
    const int wid  = tid >> 5;
    const int wm   = wid >> 2;
    const int wn   = wid & 3;
    const int i0   = blockIdx.x * CTA_M;

    const int xr = tid >> 2;
    const int xk = (tid & 3) * 8;

    float acc[2][8][4];
#pragma unroll
    for (int mt = 0; mt < 2; mt++)
#pragma unroll
        for (int nt = 0; nt < 8; nt++)
#pragma unroll
            for (int q = 0; q < 4; q++) acc[mt][nt][q] = 0.f;

    const uint32_t sb = smem_u32(smem);
    const uint32_t aBase = sb + XA_OFF + ((wm * 32 + (lane & 15)) * BSTRIDE + (lane >> 4) * 8) * 2;
    const uint32_t bBase = sb + XB_OFF + ((wn * 64 + (lane & 15)) * BSTRIDE + (lane >> 4) * 8) * 2;

    float4 xa = *reinterpret_cast<const float4*>(&x[(size_t)(i0 + xr) * FIN + xk]);
    float4 xb = *reinterpret_cast<const float4*>(&x[(size_t)(i0 + xr) * FIN + xk + 4]);
    {
        uint32_t bdst = sb + XB_OFF + tid * (BSTRIDE * 2);
        const __half* bsrc = g_W16T + (size_t)tid * FIN;
#pragma unroll
        for (int q = 0; q < 4; q++) cp16(bdst + 16 * q, bsrc + 8 * q);
        cp_commit();
    }

    for (int c = 0; c < FIN / 32; c++) {
        const int cur = c & 1;
        cp_wait_all();
        __syncthreads();

        {
            __half2 hx[4];
            hx[0] = __floats2half2_rn(xa.x, xa.y);
            hx[1] = __floats2half2_rn(xa.z, xa.w);
            hx[2] = __floats2half2_rn(xb.x, xb.y);
            hx[3] = __floats2half2_rn(xb.z, xb.w);
            *reinterpret_cast<uint4*>(smem + XA_OFF + (cur * CTA_M * BSTRIDE + xr * BSTRIDE + xk) * 2) =
                *reinterpret_cast<uint4*>(hx);
        }
        if (c + 1 < FIN / 32) {
            const int k0 = (c + 1) * 32;
            xa = *reinterpret_cast<const float4*>(&x[(size_t)(i0 + xr) * FIN + k0 + xk]);
            xb = *reinterpret_cast<const float4*>(&x[(size_t)(i0 + xr) * FIN + k0 + xk + 4]);
            uint32_t bdst = sb + XB_OFF + ((cur ^ 1) * FOUT * BSTRIDE + tid * BSTRIDE) * 2;
            const __half* bsrc = g_W16T + (size_t)tid * FIN + k0;
#pragma unroll
            for (int q = 0; q < 4; q++) cp16(bdst + 16 * q, bsrc + 8 * q);
        }
        cp_commit();
        __syncthreads();

        const uint32_t aOff = cur * (uint32_t)(CTA_M * BSTRIDE * 2);
        const uint32_t bOff = cur * (uint32_t)(FOUT * BSTRIDE * 2);
#pragma unroll
        for (int ks = 0; ks < 2; ks++) {
            const uint32_t kOff = ks * 32;
            uint32_t af[2][4];
            ldsm4(af[0], aBase + aOff + kOff);
            ldsm4(af[1], aBase + aOff + kOff + 16 * BSTRIDE * 2);
            uint32_t bf[4][4];
#pragma unroll
            for (int np = 0; np < 4; np++)
                ldsm4(bf[np], bBase + bOff + kOff + np * 16 * BSTRIDE * 2);
#pragma unroll
            for (int np = 0; np < 4; np++) {
#pragma unroll
                for (int mt = 0; mt < 2; mt++) {
                    mma16816(acc[mt][2 * np],     af[mt], bf[np][0], bf[np][2]);
                    mma16816(acc[mt][2 * np + 1], af[mt], bf[np][1], bf[np][3]);
                }
            }
        }
        __syncthreads();
    }

    // ---- epilogue: smem transpose -> block-tiled pre-swizzled gmem ----
    __half* Dp = reinterpret_cast<__half*>(smem + XD_OFF);   // [64][264]
#pragma unroll
    for (int mt = 0; mt < 2; mt++) {
        const int rca = wm * 32 + mt * 16 + (lane >> 2);
        const int c0  = wn * 64 + 2 * (lane & 3);
#pragma unroll
        for (int nt = 0; nt < 8; nt++) {
            const int cc = c0 + nt * 8;
            *reinterpret_cast<__half2*>(&Dp[rca * 264 + cc]) =
                __floats2half2_rn(acc[mt][nt][0], acc[mt][nt][1]);
            *reinterpret_cast<__half2*>(&Dp[(rca + 8) * 264 + cc]) =
                __floats2half2_rn(acc[mt][nt][2], acc[mt][nt][3]);
        }
    }
    __syncthreads();

    const int ib0 = blockIdx.x * 2;
    const int m   = (tid >> 1) & 3;
#pragma unroll
    for (int blk = 0; blk < 2; blk++) {
        __half* dst = g_hT16 + (size_t)(ib0 + blk) * TILE_HALVES + tid * 32;
#pragma unroll
        for (int u = 0; u < 4; u++) {
            __half2 v[4];
#pragma unroll
            for (int w = 0; w < 4; w++)
                v[w] = __halves2half2(Dp[(blk * 32 + u * 8 + 2 * w) * 264 + tid],
                                      Dp[(blk * 32 + u * 8 + 2 * w + 1) * 264 + tid]);
            *reinterpret_cast<uint4*>(dst + ((u ^ m) << 3)) = *reinterpret_cast<uint4*>(v);
        }
    }
}

// ---------------------------------------------------------------------------
// Attention (ROUND-13 BEST, verbatim): fp16 mma, j-split, CH=32, overlapped
// single-barrier structure. Launched at index 3 so ncu captures it.
// ---------------------------------------------------------------------------
__global__ void __launch_bounds__(256, 2) k_attn_f16(const int* __restrict__ adj) {
    __shared__ __align__(16)  __half A_s[2][CTA_M][BSTRIDE];
    __shared__ __align__(128) __half B_s[2][TILE_HALVES];
    __shared__ float zs[256];
    __shared__ __align__(8) unsigned long long mbar[2];

    const int tid  = threadIdx.x;
    const int lane = tid & 31;
    const int wid  = tid >> 5;
    const int wm   = wid >> 2;
    const int wn   = wid & 3;
    const int rb   = blockIdx.x >> 1;
    const int half = blockIdx.x & 1;
    const int i0   = rb * CTA_M;
    const int jb   = half * JHALF;
    const int jblk0 = jb >> 5;

    const int pr = tid >> 2;
    const int kq = (tid & 3) * 8;

    const float2 rt = g_RT[i0 + pr];
    const float Ri = rt.x, Ti = rt.y;
    float zacc = 0.f;

    float acc[2][8][4];
#pragma unroll
    for (int mt = 0; mt < 2; mt++)
#pragma unroll
        for (int nt = 0; nt < 8; nt++)
#pragma unroll
            for (int q = 0; q < 4; q++) acc[mt][nt][q] = 0.f;

    const uint32_t aAddrBase = smem_u32(&A_s[0][wm * 32 + (lane & 15)][(lane >> 4) * 8]);
    const uint32_t bTile0    = smem_u32(&B_s[0][0]);
    const uint32_t mb0       = smem_u32(&mbar[0]);

    uint32_t bRowOff[4], bM[4];
#pragma unroll
    for (int np = 0; np < 4; np++) {
        const int r = wn * 64 + np * 16 + (lane & 15);
        bRowOff[np] = (uint32_t)r * 64u;
        bM[np] = (uint32_t)((r >> 1) & 3);
    }
    const uint32_t cHi = (uint32_t)(lane >> 4);

    if (tid == 0) {
        MBAR_INIT(mb0,     1u);
        MBAR_INIT(mb0 + 8, 1u);
    }
    __syncthreads();

    if (tid == 0) {
        MBAR_EXPECT_TX(mb0, 16384u);
        CP_BULK(bTile0, (const char*)(g_hT16 + (size_t)jblk0 * TILE_HALVES), 16384u, mb0);
    }
    const int4* arow = reinterpret_cast<const int4*>(adj + (size_t)(i0 + pr) * NN + jb);
    {
        int4 a0 = arow[kq >> 2];
        int4 a1 = arow[(kq >> 2) + 1];
        const float4* efg = g_EFG + jb;
        int avv[8] = {a0.x, a0.y, a0.z, a0.w, a1.x, a1.y, a1.z, a1.w};
        __half2 hp[4];
#pragma unroll
        for (int u = 0; u < 8; u += 2) {
            float4 e0 = __ldg(&efg[kq + u]);
            float4 e1 = __ldg(&efg[kq + u + 1]);
            float p0 = (e0.z > Ti) ? e0.x : Ri * e0.y;
            float p1 = (e1.z > Ti) ? e1.x : Ri * e1.y;
            p0 = (avv[u] > 0) ? p0 : 0.f;
            p1 = (avv[u + 1] > 0) ? p1 : 0.f;
            zacc += p0 + p1;
            hp[u >> 1] = __floats2half2_rn(p0, p1);
        }
        *reinterpret_cast<uint4*>(&A_s[0][pr][kq]) = *reinterpret_cast<uint4*>(hp);
    }
    __syncthreads();

    for (int c = 0; c < NCH_H; c++) {
        const int cur = c & 1, nxt = cur ^ 1;

        if (tid == 0 && c + 1 < NCH_H) {
            const uint32_t mbn = mb0 + 8u * (uint32_t)nxt;
            MBAR_EXPECT_TX(mbn, 16384u);
            CP_BULK(bTile0 + (uint32_t)nxt * TILE_BYTES,
                    (const char*)(g_hT16 + (size_t)(jblk0 + c + 1) * TILE_HALVES), 16384u, mbn);
        }
        int4 a0, a1;
        if (c + 1 < NCH_H) {
            const int ji = ((c + 1) * CH + kq) >> 2;
            a0 = arow[ji];
            a1 = arow[ji + 1];
        }

        MBAR_WAIT(mb0 + 8u * (uint32_t)cur, (c >> 1) & 1);

        const uint32_t aBufBase = aAddrBase + (uint32_t)cur * ABUF_BYTES;
        const uint32_t bBufBase = bTile0 + (uint32_t)cur * TILE_BYTES;
#pragma unroll
        for (int ks = 0; ks < 2; ks++) {
            const uint32_t kOff = ks * 32;
            uint32_t af[2][4];
            ldsm4(af[0], aBufBase + kOff);
            ldsm4(af[1], aBufBase + kOff + 16 * BSTRIDE * 2);
            const uint32_t c16 = cHi + 2u * (uint32_t)ks;
            uint32_t bf[4][4];
#pragma unroll
            for (int np = 0; np < 4; np++)
                ldsm4(bf[np], bBufBase + bRowOff[np] + (((c16 ^ bM[np])) << 4));
#pragma unroll
            for (int np = 0; np < 4; np++) {
#pragma unroll
                for (int mt = 0; mt < 2; mt++) {
                    mma16816(acc[mt][2 * np],     af[mt], bf[np][0], bf[np][2]);
                    mma16816(acc[mt][2 * np + 1], af[mt], bf[np][1], bf[np][3]);
                }
            }
        }

        if (c + 1 < NCH_H) {
            const float4* efg = g_EFG + jb + (c + 1) * CH;
            int avv[8] = {a0.x, a0.y, a0.z, a0.w, a1.x, a1.y, a1.z, a1.w};
            __half2 hp[4];
#pragma unroll
            for (int u = 0; u < 8; u += 2) {
                float4 e0 = __ldg(&efg[kq + u]);
                float4 e1 = __ldg(&efg[kq + u + 1]);
                float p0 = (e0.z > Ti) ? e0.x : Ri * e0.y;
                float p1 = (e1.z > Ti) ? e1.x : Ri * e1.y;
                p0 = (avv[u] > 0) ? p0 : 0.f;
                p1 = (avv[u + 1] > 0) ? p1 : 0.f;
                zacc += p0 + p1;
                hp[u >> 1] = __floats2half2_rn(p0, p1);
            }
            *reinterpret_cast<uint4*>(&A_s[nxt][pr][kq]) = *reinterpret_cast<uint4*>(hp);
        }

        __syncthreads();
    }

    zs[tid] = zacc;
    __syncthreads();
    if (tid < CTA_M)
        g_Z[half][i0 + tid] = zs[4 * tid] + zs[4 * tid + 1] + zs[4 * tid + 2] + zs[4 * tid + 3];

    float* Sp = g_S[half];
#pragma unroll
    for (int mt = 0; mt < 2; mt++) {
        const int rca = wm * 32 + mt * 16 + (lane >> 2);
        float* o0 = Sp + (size_t)(i0 + rca) * FOUT;
        float* o1 = Sp + (size_t)(i0 + rca + 8) * FOUT;
#pragma unroll
        for (int nt = 0; nt < 8; nt++) {
            const int colb = wn * 64 + nt * 8 + 2 * (lane & 3);
            *reinterpret_cast<float2*>(o0 + colb) = make_float2(acc[mt][nt][0], acc[mt][nt][1]);
            *reinterpret_cast<float2*>(o1 + colb) = make_float2(acc[mt][nt][2], acc[mt][nt][3]);
        }
    }
}

// ---------------------------------------------------------------------------
// Combine halves (vectorized): out = (S0+S1) / (Z0+Z1). 4 rows / CTA, float4.
// ---------------------------------------------------------------------------
__global__ void __launch_bounds__(256) k_combine(float* __restrict__ out) {
    const int t   = threadIdx.x;
    const int i   = blockIdx.x * 4 + (t >> 6);
    const int c4  = (t & 63) * 4;
    const float inv = 1.0f / (g_Z[0][i] + g_Z[1][i]);
    const size_t idx = (size_t)i * FOUT + c4;
    float4 s0 = *reinterpret_cast<const float4*>(&g_S[0][idx]);
    float4 s1 = *reinterpret_cast<const float4*>(&g_S[1][idx]);
    *reinterpret_cast<float4*>(&out[idx]) =
        make_float4((s0.x + s1.x) * inv, (s0.y + s1.y) * inv,
                    (s0.z + s1.z) * inv, (s0.w + s1.w) * inv);
}

// ---------------------------------------------------------------------------
extern "C" void kernel_launch(void* const* d_in, const int* in_sizes, int n_in,
                              void* d_out, int out_size) {
    const float* x   = (const float*)d_in[0];
    const int*   adj = (const int*)  d_in[1];
    const float* W   = (const float*)d_in[2];
    const float* a   = (const float*)d_in[3];
    float* out = (float*)d_out;

    cudaFuncSetAttribute(k_xw_f16, cudaFuncAttributeMaxDynamicSharedMemorySize, XW_SMEM);

    k_prep<<<FIN / 8, 256>>>(W, a);                 // launch 0
    k_xw_f16<<<NN / CTA_M, 256, XW_SMEM>>>(x);      // launch 1
    k_scores<<<NN / 8, 256>>>(x);                   // launch 2
    k_attn_f16<<<(NN / CTA_M) * 2, 256>>>(adj);     // launch 3  <- ncu capture
    k_combine<<<NN / 4, 256>>>(out);                // launch 4
}

// round 16
// speedup vs baseline: 1.0876x; 1.0416x over previous
#include <cuda_runtime.h>
#include <cuda_fp16.h>
#include <cstdint>

#define NN 8192
#define FIN 512
#define FOUT 256
#define CH 32
#define CTA_M 64
#define JHALF (NN / 2)
#define NCH_H (JHALF / CH)      // 128 chunks per half
#define BSTRIDE 40              // smem stride (halves)
#define TILE_HALVES 8192        // one 32-j tile: 256 rows * 32 halves
#define TILE_BYTES 16384
#define ABUF_BYTES (CTA_M * BSTRIDE * 2)

// ---------------- scratch (device globals; no allocation allowed) -----------
__device__ __half  g_hT16[(size_t)FOUT * NN];
__device__ __half  g_W16T[(size_t)FOUT * FIN];
__device__ float   g_wl[FIN], g_wr[FIN];
__device__ float4  g_EFG[NN];                   // per-j: (E, F, G, 0)
__device__ float2  g_RT [NN];                   // per-i: (R=e^{-0.8f}, T=-f)
__device__ float   g_S[2][(size_t)NN * FOUT];
__device__ float   g_Z[2][NN];

// ---------------- helpers ----------------------------------------------------
static __device__ __forceinline__ uint32_t smem_u32(const void* p) {
    uint32_t a;
    asm("{ .reg .u64 t; cvta.to.shared.u64 t, %1; cvt.u32.u64 %0, t; }" : "=r"(a) : "l"(p));
    return a;
}
static __device__ __forceinline__ void cp16(uint32_t dst, const void* src) {
    asm volatile("cp.async.ca.shared.global [%0], [%1], 16;" :: "r"(dst), "l"(src));
}
static __device__ __forceinline__ void cp_commit() {
    asm volatile("cp.async.commit_group;");
}
static __device__ __forceinline__ void cp_wait_all() {
    asm volatile("cp.async.wait_group 0;");
}
static __device__ __forceinline__ void ldsm4(uint32_t* r, uint32_t addr) {
    asm volatile("ldmatrix.sync.aligned.m8n8.x4.shared.b16 {%0,%1,%2,%3}, [%4];"
                 : "=r"(r[0]), "=r"(r[1]), "=r"(r[2]), "=r"(r[3]) : "r"(addr));
}
static __device__ __forceinline__ void mma16816(float* d, const uint32_t* a,
                                                uint32_t b0, uint32_t b1) {
    asm volatile(
        "mma.sync.aligned.m16n8k16.row.col.f32.f16.f16.f32 "
        "{%0,%1,%2,%3}, {%4,%5,%6,%7}, {%8,%9}, {%0,%1,%2,%3};"
        : "+f"(d[0]), "+f"(d[1]), "+f"(d[2]), "+f"(d[3])
        : "r"(a[0]), "r"(a[1]), "r"(a[2]), "r"(a[3]), "r"(b0), "r"(b1));
}

#define MBAR_INIT(addr, cnt) \
    asm volatile("mbarrier.init.shared.b64 [%0], %1;" :: "r"(addr), "r"(cnt) : "memory")
#define MBAR_EXPECT_TX(addr, tx) \
    asm volatile("mbarrier.arrive.expect_tx.shared.b64 _, [%0], %1;" :: "r"(addr), "r"(tx) : "memory")
#define MBAR_ARRIVE(addr) \
    asm volatile("mbarrier.arrive.shared.b64 _, [%0];" :: "r"(addr) : "memory")
#define CP_BULK(dst, src, bytes, mbar) \
    asm volatile("cp.async.bulk.shared::cta.global.mbarrier::complete_tx::bytes " \
                 "[%0], [%1], %2, [%3];" \
                 :: "r"(dst), "l"(src), "r"(bytes), "r"(mbar) : "memory")
#define MBAR_WAIT(addr, par) do {                                              \
    uint32_t _m = (addr), _p = (par), _d;                                      \
    asm volatile("{\n\t.reg .pred p;\n\t"                                      \
        "mbarrier.try_wait.parity.acquire.cta.shared::cta.b64 p, [%1], %2;\n\t"\
        "selp.b32 %0, 1, 0, p;\n\t}"                                           \
        : "=r"(_d) : "r"(_m), "r"(_p) : "memory");                             \
    if (!_d) {                                                                 \
        asm volatile("{\n\t.reg .pred P1;\n\t"                                 \
            "WL_%=:\n\t"                                                       \
            "mbarrier.try_wait.parity.acquire.cta.shared::cta.b64 P1, [%0], %1, 0x989680;\n\t" \
            "@P1 bra.uni WD_%=;\n\t"                                           \
            "bra.uni WL_%=;\n\t"                                               \
            "WD_%=:\n\t}" :: "r"(_m), "r"(_p) : "memory");                     \
    }                                                                          \
} while (0)
#define GROUP_BAR(grp) \
    asm volatile("bar.sync %0, %1;" :: "r"((grp) + 1), "r"(128) : "memory")

// ---------------------------------------------------------------------------
// Prep (FUSED): W -> fp16 transposed [n][k]  AND  wl/wr = W @ a halves.
// ---------------------------------------------------------------------------
__global__ void __launch_bounds__(256) k_prep(const float* __restrict__ W,
                                              const float* __restrict__ a) {
    const int tid = threadIdx.x;
#pragma unroll
    for (int r = 0; r < 8; r++) {
        const int k = blockIdx.x * 8 + r;
        g_W16T[(size_t)tid * FIN + k] = __float2half_rn(W[(size_t)k * FOUT + tid]);
    }
    const int wid  = tid >> 5;
    const int lane = tid & 31;
    const int k    = blockIdx.x * 8 + wid;
    float l = 0.f, r = 0.f;
#pragma unroll
    for (int q = 0; q < 8; q++) {
        const int c = q * 32 + lane;
        const float wv = W[(size_t)k * FOUT + c];
        l += wv * a[c];
        r += wv * a[FOUT + c];
    }
#pragma unroll
    for (int off = 16; off; off >>= 1) {
        l += __shfl_down_sync(0xffffffffu, l, off);
        r += __shfl_down_sync(0xffffffffu, r, off);
    }
    if (lane == 0) { g_wl[k] = l; g_wr[k] = r; }
}

// ---------------------------------------------------------------------------
// Scores directly from x (fp32 exact)
// ---------------------------------------------------------------------------
__global__ void __launch_bounds__(256) k_scores(const float* __restrict__ x) {
    const int wid  = threadIdx.x >> 5;
    const int lane = threadIdx.x & 31;
    const int i    = blockIdx.x * 8 + wid;

    float f = 0.f, g = 0.f;
#pragma unroll
    for (int q = 0; q < 4; q++) {
        const int k = q * 128 + lane * 4;
        float4 xv = *reinterpret_cast<const float4*>(&x[(size_t)i * FIN + k]);
        float4 lv = *reinterpret_cast<const float4*>(&g_wl[k]);
        float4 rv = *reinterpret_cast<const float4*>(&g_wr[k]);
        f += xv.x * lv.x + xv.y * lv.y + xv.z * lv.z + xv.w * lv.w;
        g += xv.x * rv.x + xv.y * rv.y + xv.z * rv.z + xv.w * rv.w;
    }
#pragma unroll
    for (int off = 16; off; off >>= 1) {
        f += __shfl_down_sync(0xffffffffu, f, off);
        g += __shfl_down_sync(0xffffffffu, g, off);
    }
    if (lane == 0) {
        g_EFG[i] = make_float4(expf(g), expf(0.2f * g), g, 0.f);
        g_RT[i]  = make_float2(expf(-0.8f * f), -f);
    }
}

// ---------------------------------------------------------------------------
// h = x @ W via fp16 mma; epilogue writes block-tiled PRE-SWIZZLED g_hT16.
// ---------------------------------------------------------------------------
#define XA_OFF 0
#define XB_OFF 10240
#define XD_OFF 10240
#define XW_SMEM 51200

__global__ void __launch_bounds__(256) k_xw_f16(const float* __restrict__ x) {
    extern __shared__ char smem[];
    const int tid  = threadIdx.x;
    const int lane = tid & 31;
    const int wid  = tid >> 5;
    const int wm   = wid >> 2;
    const int wn   = wid & 3;
    const int i0   = blockIdx.x * CTA_M;

    const int xr = tid >> 2;
    const int xk = (tid & 3) * 8;

    float acc[2][8][4];
#pragma unroll
    for (int mt = 0; mt < 2; mt++)
#pragma unroll
        for (int nt = 0; nt < 8; nt++)
#pragma unroll
            for (int q = 0; q < 4; q++) acc[mt][nt][q] = 0.f;

    const uint32_t sb = smem_u32(smem);
    const uint32_t aBase = sb + XA_OFF + ((wm * 32 + (lane & 15)) * BSTRIDE + (lane >> 4) * 8) * 2;
    const uint32_t bBase = sb + XB_OFF + ((wn * 64 + (lane & 15)) * BSTRIDE + (lane >> 4) * 8) * 2;

    float4 xa = *reinterpret_cast<const float4*>(&x[(size_t)(i0 + xr) * FIN + xk]);
    float4 xb = *reinterpret_cast<const float4*>(&x[(size_t)(i0 + xr) * FIN + xk + 4]);
    {
        uint32_t bdst = sb + XB_OFF + tid * (BSTRIDE * 2);
        const __half* bsrc = g_W16T + (size_t)tid * FIN;
#pragma unroll
        for (int q = 0; q < 4; q++) cp16(bdst + 16 * q, bsrc + 8 * q);
        cp_commit();
    }

    for (int c = 0; c < FIN / 32; c++) {
        const int cur = c & 1;
        cp_wait_all();
        __syncthreads();

        {
            __half2 hx[4];
            hx[0] = __floats2half2_rn(xa.x, xa.y);
            hx[1] = __floats2half2_rn(xa.z, xa.w);
            hx[2] = __floats2half2_rn(xb.x, xb.y);
            hx[3] = __floats2half2_rn(xb.z, xb.w);
            *reinterpret_cast<uint4*>(smem + XA_OFF + (cur * CTA_M * BSTRIDE + xr * BSTRIDE + xk) * 2) =
                *reinterpret_cast<uint4*>(hx);
        }
        if (c + 1 < FIN / 32) {
            const int k0 = (c + 1) * 32;
            xa = *reinterpret_cast<const float4*>(&x[(size_t)(i0 + xr) * FIN + k0 + xk]);
            xb = *reinterpret_cast<const float4*>(&x[(size_t)(i0 + xr) * FIN + k0 + xk + 4]);
            uint32_t bdst = sb + XB_OFF + ((cur ^ 1) * FOUT * BSTRIDE + tid * BSTRIDE) * 2;
            const __half* bsrc = g_W16T + (size_t)tid * FIN + k0;
#pragma unroll
            for (int q = 0; q < 4; q++) cp16(bdst + 16 * q, bsrc + 8 * q);
        }
        cp_commit();
        __syncthreads();

        const uint32_t aOff = cur * (uint32_t)(CTA_M * BSTRIDE * 2);
        const uint32_t bOff = cur * (uint32_t)(FOUT * BSTRIDE * 2);
#pragma unroll
        for (int ks = 0; ks < 2; ks++) {
            const uint32_t kOff = ks * 32;
            uint32_t af[2][4];
            ldsm4(af[0], aBase + aOff + kOff);
            ldsm4(af[1], aBase + aOff + kOff + 16 * BSTRIDE * 2);
            uint32_t bf[4][4];
#pragma unroll
            for (int np = 0; np < 4; np++)
                ldsm4(bf[np], bBase + bOff + kOff + np * 16 * BSTRIDE * 2);
#pragma unroll
            for (int np = 0; np < 4; np++) {
#pragma unroll
                for (int mt = 0; mt < 2; mt++) {
                    mma16816(acc[mt][2 * np],     af[mt], bf[np][0], bf[np][2]);
                    mma16816(acc[mt][2 * np + 1], af[mt], bf[np][1], bf[np][3]);
                }
            }
        }
        __syncthreads();
    }

    __half* Dp = reinterpret_cast<__half*>(smem + XD_OFF);   // [64][264]
#pragma unroll
    for (int mt = 0; mt < 2; mt++) {
        const int rca = wm * 32 + mt * 16 + (lane >> 2);
        const int c0  = wn * 64 + 2 * (lane & 3);
#pragma unroll
        for (int nt = 0; nt < 8; nt++) {
            const int cc = c0 + nt * 8;
            *reinterpret_cast<__half2*>(&Dp[rca * 264 + cc]) =
                __floats2half2_rn(acc[mt][nt][0], acc[mt][nt][1]);
            *reinterpret_cast<__half2*>(&Dp[(rca + 8) * 264 + cc]) =
                __floats2half2_rn(acc[mt][nt][2], acc[mt][nt][3]);
        }
    }
    __syncthreads();

    const int ib0 = blockIdx.x * 2;
    const int m   = (tid >> 1) & 3;
#pragma unroll
    for (int blk = 0; blk < 2; blk++) {
        __half* dst = g_hT16 + (size_t)(ib0 + blk) * TILE_HALVES + tid * 32;
#pragma unroll
        for (int u = 0; u < 4; u++) {
            __half2 v[4];
#pragma unroll
            for (int w = 0; w < 4; w++)
                v[w] = __halves2half2(Dp[(blk * 32 + u * 8 + 2 * w) * 264 + tid],
                                      Dp[(blk * 32 + u * 8 + 2 * w + 1) * 264 + tid]);
            *reinterpret_cast<uint4*>(dst + ((u ^ m) << 3)) = *reinterpret_cast<uint4*>(v);
        }
    }
}

// ---------------------------------------------------------------------------
// Attention: R15 structure, but the full-CTA barrier is replaced by TWO
// 128-thread named barriers (rows 0-31 / 32-63 are group-local for both
// P-gen and mma). Cross-group B-stage reuse is guarded by empty[] mbarriers
// (arrive-count 2). Groups run desynchronized -> staggered L1 phases.
// ---------------------------------------------------------------------------
__global__ void __launch_bounds__(256, 2) k_attn_f16(const int* __restrict__ adj) {
    __shared__ __align__(16)  __half A_s[2][CTA_M][BSTRIDE];
    __shared__ __align__(128) __half B_s[2][TILE_HALVES];
    __shared__ float zs[256];
    __shared__ __align__(8) unsigned long long mbar[4];   // full0 full1 empty0 empty1

    const int tid  = threadIdx.x;
    const int lane = tid & 31;
    const int wid  = tid >> 5;
    const int wm   = wid >> 2;          // == group id (0: thr 0-127, 1: thr 128-255)
    const int wn   = wid & 3;
    const int rb   = blockIdx.x >> 1;
    const int half = blockIdx.x & 1;
    const int i0   = rb * CTA_M;
    const int jb   = half * JHALF;
    const int jblk0 = jb >> 5;

    const int pr = tid >> 2;            // P-gen row 0..63 (row>>5 == wm: group-local)
    const int kq = (tid & 3) * 8;

    const float2 rt = g_RT[i0 + pr];
    const float Ri = rt.x, Ti = rt.y;
    float zacc = 0.f;

    float acc[2][8][4];
#pragma unroll
    for (int mt = 0; mt < 2; mt++)
#pragma unroll
        for (int nt = 0; nt < 8; nt++)
#pragma unroll
            for (int q = 0; q < 4; q++) acc[mt][nt][q] = 0.f;

    const uint32_t aAddrBase = smem_u32(&A_s[0][wm * 32 + (lane & 15)][(lane >> 4) * 8]);
    const uint32_t bTile0    = smem_u32(&B_s[0][0]);
    const uint32_t mbF       = smem_u32(&mbar[0]);
    const uint32_t mbE       = smem_u32(&mbar[2]);

    uint32_t bRowOff[4], bM[4];
#pragma unroll
    for (int np = 0; np < 4; np++) {
        const int r = wn * 64 + np * 16 + (lane & 15);
        bRowOff[np] = (uint32_t)r * 64u;
        bM[np] = (uint32_t)((r >> 1) & 3);
    }
    const uint32_t cHi = (uint32_t)(lane >> 4);

    if (tid == 0) {
        MBAR_INIT(mbF,     1u);
        MBAR_INIT(mbF + 8, 1u);
        MBAR_INIT(mbE,     2u);
        MBAR_INIT(mbE + 8, 2u);
    }
    __syncthreads();   // mbar init visible to all

    // prologue: bulk B chunk 0 -> stage 0; P-gen chunk 0 into A[0]
    if (tid == 0) {
        MBAR_EXPECT_TX(mbF, 16384u);
        CP_BULK(bTile0, (const char*)(g_hT16 + (size_t)jblk0 * TILE_HALVES), 16384u, mbF);
    }
    const int4* arow = reinterpret_cast<const int4*>(adj + (size_t)(i0 + pr) * NN + jb);
    {
        int4 a0 = arow[kq >> 2];
        int4 a1 = arow[(kq >> 2) + 1];
        const float4* efg = g_EFG + jb;
        int avv[8] = {a0.x, a0.y, a0.z, a0.w, a1.x, a1.y, a1.z, a1.w};
        __half2 hp[4];
#pragma unroll
        for (int u = 0; u < 8; u += 2) {
            float4 e0 = __ldg(&efg[kq + u]);
            float4 e1 = __ldg(&efg[kq + u + 1]);
            float p0 = (e0.z > Ti) ? e0.x : Ri * e0.y;
            float p1 = (e1.z > Ti) ? e1.x : Ri * e1.y;
            p0 = (avv[u] > 0) ? p0 : 0.f;
            p1 = (avv[u + 1] > 0) ? p1 : 0.f;
            zacc += p0 + p1;
            hp[u >> 1] = __floats2half2_rn(p0, p1);
        }
        *reinterpret_cast<uint4*>(&A_s[0][pr][kq]) = *reinterpret_cast<uint4*>(hp);
    }
    GROUP_BAR(wm);   // publish A[0] within group

    for (int c = 0; c < NCH_H; c++) {
        const int cur = c & 1, nxt = cur ^ 1;

        // producer: issue bulk for chunk k=c+1 into stage nxt.
        // For k>=2 wait empty[nxt] (both groups done reading it at chunk k-2).
        if (tid == 0 && c + 1 < NCH_H) {
            const int k = c + 1;
            const uint32_t mbn = mbF + 8u * (uint32_t)nxt;
            if (k >= 2) MBAR_WAIT(mbE + 8u * (uint32_t)(k & 1), ((k >> 1) & 1) ^ 1);
            MBAR_EXPECT_TX(mbn, 16384u);
            CP_BULK(bTile0 + (uint32_t)nxt * TILE_BYTES,
                    (const char*)(g_hT16 + (size_t)(jblk0 + c + 1) * TILE_HALVES), 16384u, mbn);
        }
        int4 a0, a1;
        if (c + 1 < NCH_H) {
            const int ji = ((c + 1) * CH + kq) >> 2;
            a0 = arow[ji];
            a1 = arow[ji + 1];
        }

        MBAR_WAIT(mbF + 8u * (uint32_t)cur, (c >> 1) & 1);   // chunk c's B tile

        // ---- mma on chunk c ----
        const uint32_t aBufBase = aAddrBase + (uint32_t)cur * ABUF_BYTES;
        const uint32_t bBufBase = bTile0 + (uint32_t)cur * TILE_BYTES;
#pragma unroll
        for (int ks = 0; ks < 2; ks++) {
            const uint32_t kOff = ks * 32;
            uint32_t af[2][4];
            ldsm4(af[0], aBufBase + kOff);
            ldsm4(af[1], aBufBase + kOff + 16 * BSTRIDE * 2);
            const uint32_t c16 = cHi + 2u * (uint32_t)ks;
            uint32_t bf[4][4];
#pragma unroll
            for (int np = 0; np < 4; np++)
                ldsm4(bf[np], bBufBase + bRowOff[np] + (((c16 ^ bM[np])) << 4));
#pragma unroll
            for (int np = 0; np < 4; np++) {
#pragma unroll
                for (int mt = 0; mt < 2; mt++) {
                    mma16816(acc[mt][2 * np],     af[mt], bf[np][0], bf[np][2]);
                    mma16816(acc[mt][2 * np + 1], af[mt], bf[np][1], bf[np][3]);
                }
            }
        }

        // ---- P-gen chunk c+1 into A[nxt] (group-local rows) ----
        if (c + 1 < NCH_H) {
            const float4* efg = g_EFG + jb + (c + 1) * CH;
            int avv[8] = {a0.x, a0.y, a0.z, a0.w, a1.x, a1.y, a1.z, a1.w};
            __half2 hp[4];
#pragma unroll
            for (int u = 0; u < 8; u += 2) {
                float4 e0 = __ldg(&efg[kq + u]);
                float4 e1 = __ldg(&efg[kq + u + 1]);
                float p0 = (e0.z > Ti) ? e0.x : Ri * e0.y;
                float p1 = (e1.z > Ti) ? e1.x : Ri * e1.y;
                p0 = (avv[u] > 0) ? p0 : 0.f;
                p1 = (avv[u + 1] > 0) ? p1 : 0.f;
                zacc += p0 + p1;
                hp[u >> 1] = __floats2half2_rn(p0, p1);
            }
            *reinterpret_cast<uint4*>(&A_s[nxt][pr][kq]) = *reinterpret_cast<uint4*>(hp);
        }

        GROUP_BAR(wm);   // group done: A[nxt] published, B[cur]/A[cur] reads done
        if ((tid & 127) == 0)
            MBAR_ARRIVE(mbE + 8u * (uint32_t)cur);   // group signals B[cur] free
    }

    // ---- converge both groups, then row sums + store ----
    zs[tid] = zacc;
    __syncthreads();
    if (tid < CTA_M)
        g_Z[half][i0 + tid] = zs[4 * tid] + zs[4 * tid + 1] + zs[4 * tid + 2] + zs[4 * tid + 3];

    float* Sp = g_S[half];
#pragma unroll
    for (int mt = 0; mt < 2; mt++) {
        const int rca = wm * 32 + mt * 16 + (lane >> 2);
        float* o0 = Sp + (size_t)(i0 + rca) * FOUT;
        float* o1 = Sp + (size_t)(i0 + rca + 8) * FOUT;
#pragma unroll
        for (int nt = 0; nt < 8; nt++) {
            const int colb = wn * 64 + nt * 8 + 2 * (lane & 3);
            *reinterpret_cast<float2*>(o0 + colb) = make_float2(acc[mt][nt][0], acc[mt][nt][1]);
            *reinterpret_cast<float2*>(o1 + colb) = make_float2(acc[mt][nt][2], acc[mt][nt][3]);
        }
    }
}

// ---------------------------------------------------------------------------
// Combine halves (vectorized): out = (S0+S1) / (Z0+Z1)
// ---------------------------------------------------------------------------
__global__ void __launch_bounds__(256) k_combine(float* __restrict__ out) {
    const int t   = threadIdx.x;
    const int i   = blockIdx.x * 4 + (t >> 6);
    const int c4  = (t & 63) * 4;
    const float inv = 1.0f / (g_Z[0][i] + g_Z[1][i]);
    const size_t idx = (size_t)i * FOUT + c4;
    float4 s0 = *reinterpret_cast<const float4*>(&g_S[0][idx]);
    float4 s1 = *reinterpret_cast<const float4*>(&g_S[1][idx]);
    *reinterpret_cast<float4*>(&out[idx]) =
        make_float4((s0.x + s1.x) * inv, (s0.y + s1.y) * inv,
                    (s0.z + s1.z) * inv, (s0.w + s1.w) * inv);
}

// ---------------------------------------------------------------------------
extern "C" void kernel_launch(void* const* d_in, const int* in_sizes, int n_in,
                              void* d_out, int out_size) {
    const float* x   = (const float*)d_in[0];
    const int*   adj = (const int*)  d_in[1];
    const float* W   = (const float*)d_in[2];
    const float* a   = (const float*)d_in[3];
    float* out = (float*)d_out;

    cudaFuncSetAttribute(k_xw_f16, cudaFuncAttributeMaxDynamicSharedMemorySize, XW_SMEM);

    k_prep<<<FIN / 8, 256>>>(W, a);                 // launch 0
    k_xw_f16<<<NN / CTA_M, 256, XW_SMEM>>>(x);      // launch 1
    k_scores<<<NN / 8, 256>>>(x);                   // launch 2
    k_attn_f16<<<(NN / CTA_M) * 2, 256>>>(adj);     // launch 3  <- ncu capture
    k_combine<<<NN / 4, 256>>>(out);                // launch 4
}